// round 9
// baseline (speedup 1.0000x reference)
#include <cuda_runtime.h>
#include <cuda_fp16.h>
#include <cstdint>

// ---------------------------------------------------------------------------
// W4A16 grouped GEMM: out[32,28672] = x[32,8192] @ dequant(qweight) + bias
//   qweight int32 [K/8, N]: 8 int4 nibbles per word along K, zero-point 8
//   x / scales / bias fp16-origin delivered as f32; output f32.
//
// R8: split-K x8 with fused last-CTA reduction.
//   - __launch_bounds__(128, 6): cap regs ~85 -> 6+ CTAs/SM (R7 was reg-capped
//     at 5 CTAs/SM = 31% occ; SMEM 17.9KB allows 12).
//   - single __syncthreads per chunk (sync -> store next buf -> prefetch ->
//     compute cur buf); effective distance-2 LDG prefetch.
//   - per-tile atomic counter: last split-K CTA sums the 8 f32 partials from
//     device scratch, rounds dot through fp16, adds fp16 bias, stores f32,
//     resets counter (graph-replay deterministic). No second kernel.
// Inner math unchanged: mma.sync.m16n8k16 + ldmatrix; qweight words
// LDS-broadcast, dequantized into B frags via byte_perm + LOP3 magic-bias +
// exact HSUB2{1032,1152} / HMUL2{s,s/16} -> single fp16 rounding per weight.
// ---------------------------------------------------------------------------

static constexpr int MDIM    = 32;
static constexpr int KDIM    = 8192;
static constexpr int NDIM    = 28672;
static constexpr int NT      = 128;                 // n per CTA tile
static constexpr int KC      = 64;                  // k per chunk
static constexpr int KSPLIT  = 8;
static constexpr int CPS     = KDIM / KC / KSPLIT;  // 16 chunks per split
static constexpr int NTILES  = NDIM / NT;           // 224
static constexpr int THREADS = 128;
static constexpr int XSTRIDE = 144;                 // bytes per x row in SMEM

__device__ float g_scratch[KSPLIT * MDIM * NDIM];   // 29.36 MB partials
__device__ int   g_cnt[NTILES];                     // zero-init; reset after use

// --------------------------- PTX helpers -----------------------------------

__device__ __forceinline__ uint32_t smem_u32(const void* p) {
    uint32_t a;
    asm("{ .reg .u64 t; cvta.to.shared.u64 t, %1; cvt.u32.u64 %0, t; }"
        : "=r"(a) : "l"(p));
    return a;
}

__device__ __forceinline__ void ldmatrix_x4(uint32_t* r, uint32_t addr) {
    asm volatile(
        "ldmatrix.sync.aligned.m8n8.x4.shared.b16 {%0,%1,%2,%3}, [%4];"
        : "=r"(r[0]), "=r"(r[1]), "=r"(r[2]), "=r"(r[3]) : "r"(addr));
}

__device__ __forceinline__ void mma_16816(float* c, const uint32_t* a,
                                          uint32_t b0, uint32_t b1) {
    asm volatile(
        "mma.sync.aligned.m16n8k16.row.col.f32.f16.f16.f32 "
        "{%0,%1,%2,%3}, {%4,%5,%6,%7}, {%8,%9}, {%0,%1,%2,%3};"
        : "+f"(c[0]), "+f"(c[1]), "+f"(c[2]), "+f"(c[3])
        : "r"(a[0]), "r"(a[1]), "r"(a[2]), "r"(a[3]), "r"(b0), "r"(b1));
}

__device__ __forceinline__ uint32_t pack_h2(float a, float b) {
    __half2 h = __floats2half2_rn(a, b);
    return *reinterpret_cast<uint32_t*>(&h);
}

// --------------------------- dequant ---------------------------------------
// Byte t of word w holds (k=2t lo-nibble, k=2t+1 hi-nibble). byte_perm
// replicates byte t into bytes 0,2; mask+OR builds {1024+n_lo, 1024+16*n_hi};
// exact HSUB2 {1032,1152} then HMUL2 {s, s/16} -> {(n_lo-8)s, (n_hi-8)s}.
__device__ __forceinline__ uint32_t dq_pair(uint32_t w, uint32_t sel, uint32_t mul2u) {
    const uint32_t SUBC = 0x64806408u;  // half2 {1032, 1152}
    uint32_t v = __byte_perm(w, 0, sel);
    uint32_t p = (v & 0x00F0000Fu) | 0x64006400u;
    __half2 h = __hmul2(__hsub2(*reinterpret_cast<__half2*>(&p),
                                *reinterpret_cast<const __half2*>(&SUBC)),
                        *reinterpret_cast<__half2*>(&mul2u));
    return *reinterpret_cast<uint32_t*>(&h);
}

// --------------------------- prefetch fragment ------------------------------

struct Frag {
    uint4    qa, qb;     // 8 qweight words for staging
    uint32_t xh[8];      // 16 halfs: x rows (tid>>3), (tid>>3)+16, 8 k each
    float    sc;         // scales[c/2][n0+tid]
};

__device__ __forceinline__ Frag load_frag(int c, const uint4* __restrict__ qw4,
                                          const float4* __restrict__ x4,
                                          const float* __restrict__ scales,
                                          int tid, int n0) {
    Frag f;
    int qi = (c * 8 + (tid >> 4)) * (NDIM / 4) + (n0 >> 2) + (tid & 15);
    f.qa = qw4[qi];
    f.qb = qw4[qi + 16];
    int xi = (tid >> 3) * (KDIM / 4) + c * 16 + (tid & 7) * 2;
    float4 a0 = x4[xi], a1 = x4[xi + 1];
    float4 b0 = x4[xi + 16 * (KDIM / 4)], b1 = x4[xi + 16 * (KDIM / 4) + 1];
    f.xh[0] = pack_h2(a0.x, a0.y); f.xh[1] = pack_h2(a0.z, a0.w);
    f.xh[2] = pack_h2(a1.x, a1.y); f.xh[3] = pack_h2(a1.z, a1.w);
    f.xh[4] = pack_h2(b0.x, b0.y); f.xh[5] = pack_h2(b0.z, b0.w);
    f.xh[6] = pack_h2(b1.x, b1.y); f.xh[7] = pack_h2(b1.z, b1.w);
    f.sc = scales[(c >> 1) * NDIM + n0 + tid];
    return f;
}

// --------------------------- main kernel ------------------------------------

__global__ void __launch_bounds__(THREADS, 6)
w4a16_partial_kernel(const float* __restrict__ x,
                     const uint32_t* __restrict__ qweight,
                     const float* __restrict__ scales,
                     const float* __restrict__ bias,
                     float* __restrict__ out) {
    __shared__ uint32_t s_qw[2][8 * 128];
    __shared__ __align__(16) uint8_t s_x[2][32 * XSTRIDE];
    __shared__ __half s_sc[2][128];
    __shared__ int s_last;

    const int tid  = threadIdx.x;
    const int lane = tid & 31;
    const int wid  = tid >> 5;
    const int tile = blockIdx.x;
    const int n0   = tile * NT;
    const int ks   = blockIdx.y;
    const int c0   = ks * CPS;
    const int t4   = lane & 3;
    const uint32_t sel = 0x4040u + (uint32_t)t4 * 0x0101u;

    int nl[4];
#pragma unroll
    for (int j = 0; j < 4; ++j) nl[j] = wid * 32 + (lane >> 2) + 8 * j;

    const uint4*  qw4 = reinterpret_cast<const uint4*>(qweight);
    const float4* x4  = reinterpret_cast<const float4*>(x);
    const __half one16 = __ushort_as_half(0x2C00);   // 1/16

    uint32_t* qdst = &s_qw[0][(tid >> 4) * 128 + (tid & 15) * 4];
    uint8_t*  xdst = &s_x[0][(tid >> 3) * XSTRIDE + (tid & 7) * 16];
    const uint32_t xm_base = smem_u32(&s_x[0][0]) +
                             (uint32_t)(lane & 15) * XSTRIDE + (uint32_t)(lane >> 4) * 16;

    float acc[2][4][4];
#pragma unroll
    for (int mt = 0; mt < 2; ++mt)
#pragma unroll
        for (int j = 0; j < 4; ++j)
#pragma unroll
            for (int r = 0; r < 4; ++r) acc[mt][j][r] = 0.0f;

    // prologue: stage chunk 0 into buf0, prefetch chunk 1
    {
        Frag f0 = load_frag(c0, qw4, x4, scales, tid, n0);
        *reinterpret_cast<uint4*>(qdst)      = f0.qa;
        *reinterpret_cast<uint4*>(qdst + 64) = f0.qb;
        *reinterpret_cast<uint4*>(xdst)                = *reinterpret_cast<uint4*>(&f0.xh[0]);
        *reinterpret_cast<uint4*>(xdst + 16 * XSTRIDE) = *reinterpret_cast<uint4*>(&f0.xh[4]);
        s_sc[0][tid] = __float2half(f0.sc);
    }
    Frag pf = load_frag(c0 + 1, qw4, x4, scales, tid, n0);

    for (int ci = 0; ci < CPS; ++ci) {
        const int buf = ci & 1;
        __syncthreads();   // buf valid for compute; buf^1 free for store

        // store chunk ci+1 into buf^1 (last iteration's store is never read)
        {
            uint32_t* qd = qdst + (buf ^ 1) * (8 * 128);
            *reinterpret_cast<uint4*>(qd)      = pf.qa;
            *reinterpret_cast<uint4*>(qd + 64) = pf.qb;
            uint8_t* xd = xdst + (buf ^ 1) * (32 * XSTRIDE);
            *reinterpret_cast<uint4*>(xd)                = *reinterpret_cast<uint4*>(&pf.xh[0]);
            *reinterpret_cast<uint4*>(xd + 16 * XSTRIDE) = *reinterpret_cast<uint4*>(&pf.xh[4]);
            s_sc[buf ^ 1][tid] = __float2half(pf.sc);
        }
        // prefetch chunk ci+2 (wrap within split; harmless, never consumed)
        pf = load_frag(c0 + ((ci + 2) & (CPS - 1)), qw4, x4, scales, tid, n0);

        // compute chunk ci from buf
        uint32_t mul2[4];
#pragma unroll
        for (int j = 0; j < 4; ++j) {
            __half s = s_sc[buf][nl[j]];
            __half2 m = __halves2half2(s, __hmul(s, one16));
            mul2[j] = *reinterpret_cast<uint32_t*>(&m);
        }
        const uint32_t* qs = &s_qw[buf][0];
        const uint32_t xb = xm_base + (uint32_t)buf * (32 * XSTRIDE);

#pragma unroll
        for (int s4 = 0; s4 < 4; ++s4) {
            uint32_t a0[4], a1[4];
            ldmatrix_x4(a0, xb + s4 * 32);
            ldmatrix_x4(a1, xb + s4 * 32 + 16 * XSTRIDE);
#pragma unroll
            for (int j = 0; j < 4; ++j) {
                uint32_t w0 = qs[(2 * s4)     * 128 + nl[j]];
                uint32_t w1 = qs[(2 * s4 + 1) * 128 + nl[j]];
                uint32_t b0 = dq_pair(w0, sel, mul2[j]);
                uint32_t b1 = dq_pair(w1, sel, mul2[j]);
                mma_16816(acc[0][j], a0, b0, b1);
                mma_16816(acc[1][j], a1, b0, b1);
            }
        }
    }

    // partial epilogue: raw f32 sums to scratch[ks][m][n]
    float* sp = g_scratch + ks * (MDIM * NDIM);
#pragma unroll
    for (int j = 0; j < 4; ++j) {
        const int n = n0 + wid * 32 + j * 8 + 2 * t4;
#pragma unroll
        for (int mt = 0; mt < 2; ++mt) {
            const int m0 = mt * 16 + (lane >> 2);
            float2 v01 = { acc[mt][j][0], acc[mt][j][1] };
            float2 v23 = { acc[mt][j][2], acc[mt][j][3] };
            *reinterpret_cast<float2*>(sp + m0 * NDIM + n)       = v01;
            *reinterpret_cast<float2*>(sp + (m0 + 8) * NDIM + n) = v23;
        }
    }

    // ---- fused reduction: last CTA of this tile sums the 8 partials --------
    __threadfence();
    if (tid == 0) {
        int old = atomicAdd(&g_cnt[tile], 1);
        s_last = (old == KSPLIT - 1);
    }
    __syncthreads();
    if (!s_last) return;

    if (tid == 0) g_cnt[tile] = 0;   // reset for next launch / graph replay
    __threadfence();                 // order: counter observation -> loads

    const int n = n0 + tid;          // 128 threads : 128 columns
    const __half hb = __float2half(bias[n]);
    const float* sp0 = g_scratch + n;
#pragma unroll 4
    for (int m = 0; m < MDIM; ++m) {
        float s = 0.0f;
#pragma unroll
        for (int k = 0; k < KSPLIT; ++k)
            s += sp0[(k * MDIM + m) * NDIM];
        out[m * NDIM + n] = __half2float(__hadd(__float2half(s), hb));
    }
}

// --------------------------- launch ------------------------------------------

extern "C" void kernel_launch(void* const* d_in, const int* in_sizes, int n_in,
                              void* d_out, int out_size) {
    (void)out_size;
    const float*    x    = nullptr;   // 262144
    const uint32_t* qw   = nullptr;   // 29360128
    const float*    sc   = nullptr;   // 1835008
    const float*    bias = nullptr;   // 28672
    for (int i = 0; i < n_in; ++i) {
        switch (in_sizes[i]) {
            case MDIM * KDIM:            x    = (const float*)d_in[i];    break;
            case (KDIM / 8) * NDIM:      qw   = (const uint32_t*)d_in[i]; break;
            case (KDIM / 128) * NDIM:    sc   = (const float*)d_in[i];    break;
            case NDIM:                   bias = (const float*)d_in[i];    break;
            default: break;
        }
    }
    float* out = (float*)d_out;

    dim3 grid(NTILES, KSPLIT);   // (224, 8) = 1792 CTAs
    w4a16_partial_kernel<<<grid, THREADS>>>(x, qw, sc, bias, out);
}